// round 10
// baseline (speedup 1.0000x reference)
#include <cuda_runtime.h>
#include <cstdint>

// ---------------------------------------------------------------------------
// out = RMSNorm( x @ (mean_l conv_w[l])^T ) * norm_w
// x[16384,1024] f32, conv_w[20,1024,1024] f32, norm_w[1024] f32
// compute_103 virtual arch -> mma.sync tf32 + cp.async (no tcgen05).
// R10 = R3 resubmit (R3: device-busy; R4-R9: broker acquisition timeouts —
// kernel has never reached the GPU):
//   vectorized fragment loads via K-permutation, tf32-pre-rounded W,
//   xor-swizzled smem, 3-stage pipeline.
// ---------------------------------------------------------------------------

static constexpr int M = 16384;
static constexpr int N = 1024;
static constexpr int K = 1024;
static constexpr int L = 20;

static constexpr int BM = 128;
static constexpr int BN = 256;
static constexpr int BK = 32;
static constexpr int NKIT = K / BK;                   // 32

static constexpr int A_BYTES = BM * BK * 4;           // 16384
static constexpr int B_BYTES = BN * BK * 4;           // 32768
static constexpr int STAGE_BYTES = A_BYTES + B_BYTES; // 49152
static constexpr int NSTAGE = 3;
static constexpr int SMEM_BYTES = NSTAGE * STAGE_BYTES; // 147456

// Reduced weight matrix, values pre-rounded to tf32 (device global: no-alloc rule)
__device__ __align__(16) float g_W[N * K];            // 4 MB

// ---------------------------------------------------------------------------
// helpers
// ---------------------------------------------------------------------------
__device__ __forceinline__ uint32_t smem_u32(const void* p) {
    uint32_t a;
    asm("{ .reg .u64 t; cvta.to.shared.u64 t, %1; cvt.u32.u64 %0, t; }"
        : "=r"(a) : "l"(p));
    return a;
}

__device__ __forceinline__ uint32_t cvt_tf32(float f) {
    uint32_t u;
    asm("cvt.rna.tf32.f32 %0, %1;" : "=r"(u) : "f"(f));
    return u;
}

__device__ __forceinline__ void mma_tf32(float* c, const uint32_t* a, const uint32_t* b) {
    asm volatile(
        "mma.sync.aligned.m16n8k8.row.col.f32.tf32.tf32.f32 "
        "{%0,%1,%2,%3}, {%4,%5,%6,%7}, {%8,%9}, {%0,%1,%2,%3};"
        : "+f"(c[0]), "+f"(c[1]), "+f"(c[2]), "+f"(c[3])
        : "r"(a[0]), "r"(a[1]), "r"(a[2]), "r"(a[3]), "r"(b[0]), "r"(b[1]));
}

__device__ __forceinline__ void cp_async16(uint32_t dst_smem, const void* src) {
    asm volatile("cp.async.cg.shared.global [%0], [%1], 16;"
                 :: "r"(dst_smem), "l"(src));
}
__device__ __forceinline__ void cp_commit() {
    asm volatile("cp.async.commit_group;" ::: "memory");
}
template <int NN>
__device__ __forceinline__ void cp_wait() {
    asm volatile("cp.async.wait_group %0;" :: "n"(NN) : "memory");
}

// ---------------------------------------------------------------------------
// Kernel 1: W[o,i] = tf32_rna( (1/L) * sum_l conv_w[l,o,i] )
// ---------------------------------------------------------------------------
__global__ __launch_bounds__(256) void reduce_w_kernel(const float4* __restrict__ cw) {
    int idx = blockIdx.x * 256 + threadIdx.x;          // 0 .. 262143
    float4 acc = make_float4(0.f, 0.f, 0.f, 0.f);
#pragma unroll
    for (int l = 0; l < L; ++l) {
        float4 v = cw[(size_t)l * (N * K / 4) + idx];
        acc.x += v.x; acc.y += v.y; acc.z += v.z; acc.w += v.w;
    }
    const float s = 1.0f / (float)L;
    float4 o;
    o.x = __uint_as_float(cvt_tf32(acc.x * s));
    o.y = __uint_as_float(cvt_tf32(acc.y * s));
    o.z = __uint_as_float(cvt_tf32(acc.z * s));
    o.w = __uint_as_float(cvt_tf32(acc.w * s));
    ((float4*)g_W)[idx] = o;
}

// ---------------------------------------------------------------------------
// Kernel 2: tf32 mma.sync GEMM  y = x @ W^T  -> d_out (f32)
//   CTA 128x256x32, 8 warps at 64x64, 3-stage cp.async.
//   smem: row = 32 floats = 8 x 16B chunks; chunk s stored at s ^ (row&7).
//   K-permutation: slice s uses global columns {8t+s, 8t+s+4} so thread t's
//   fragments for all 4 slices = contiguous float8 at column 8t.
// ---------------------------------------------------------------------------
__global__ __launch_bounds__(256, 1) void gemm_tf32_kernel(const float* __restrict__ X,
                                                           float* __restrict__ Y) {
    extern __shared__ __align__(16) char smem[];
    const int tid = threadIdx.x;
    const int wid = tid >> 5;
    const int lid = tid & 31;
    const int g = lid >> 2;      // 0..7
    const int t = lid & 3;       // 0..3
    const int wm = wid >> 2;     // 0..1
    const int wn = wid & 3;      // 0..3

    const int n0 = blockIdx.x * BN;
    const int m0 = blockIdx.y * BM;

    const uint32_t sbase = smem_u32(smem);

    float acc[4][8][4];
#pragma unroll
    for (int i = 0; i < 4; ++i)
#pragma unroll
        for (int j = 0; j < 8; ++j)
#pragma unroll
            for (int q = 0; q < 4; ++q) acc[i][j][q] = 0.f;

    const float* Abase = X + (size_t)m0 * K;
    const float* Bbase = g_W + (size_t)n0 * K;

    auto load_tiles = [&](int kt, int stage) {
        const uint32_t sA = sbase + stage * STAGE_BYTES;
        const uint32_t sB = sA + A_BYTES;
        const float* Ak = Abase + kt * BK;
        const float* Bk = Bbase + kt * BK;
#pragma unroll
        for (int q = 0; q < 4; ++q) {                  // A: 1024 chunks
            int id = tid + q * 256;
            int row = id >> 3, s = id & 7;
            int phys = s ^ (row & 7);
            cp_async16(sA + (uint32_t)(row * 8 + phys) * 16,
                       Ak + (size_t)row * K + s * 4);
        }
#pragma unroll
        for (int q = 0; q < 8; ++q) {                  // B: 2048 chunks
            int id = tid + q * 256;
            int row = id >> 3, s = id & 7;
            int phys = s ^ (row & 7);
            cp_async16(sB + (uint32_t)(row * 8 + phys) * 16,
                       Bk + (size_t)row * K + s * 4);
        }
        cp_commit();
    };

    load_tiles(0, 0);
    load_tiles(1, 1);

    const int cl = (2 * t) ^ g;      // physical chunk of low half (cols 8t..8t+3)
    const int ch = (2 * t + 1) ^ g;  // physical chunk of high half (cols 8t+4..8t+7)

#pragma unroll 1
    for (int kt = 0; kt < NKIT; ++kt) {
        if (kt + 2 < NKIT) load_tiles(kt + 2, (kt + 2) % NSTAGE);

        if (kt < NKIT - 2)      cp_wait<2>();
        else if (kt == NKIT - 2) cp_wait<1>();
        else                     cp_wait<0>();
        __syncthreads();

        const char* As = smem + (kt % NSTAGE) * STAGE_BYTES;
        const char* Bs = As + A_BYTES;

        // B fragments: 8 n-rows, float8 each (already tf32-rounded in g_W)
        float4 vbl[8], vbh[8];
#pragma unroll
        for (int j = 0; j < 8; ++j) {
            int n = wn * 64 + j * 8 + g;               // n & 7 == g
            const float4* rp = (const float4*)(Bs + (size_t)n * 128);
            vbl[j] = rp[cl];
            vbh[j] = rp[ch];
        }

#pragma unroll
        for (int i = 0; i < 4; ++i) {
            int r = wm * 64 + i * 16 + g;              // r & 7 == g
            const float4* ra  = (const float4*)(As + (size_t)r * 128);
            const float4* ra8 = (const float4*)(As + (size_t)(r + 8) * 128);
            float4 al0 = ra[cl],  ah0 = ra[ch];
            float4 al1 = ra8[cl], ah1 = ra8[ch];

            uint32_t ual0[4] = {cvt_tf32(al0.x), cvt_tf32(al0.y), cvt_tf32(al0.z), cvt_tf32(al0.w)};
            uint32_t uah0[4] = {cvt_tf32(ah0.x), cvt_tf32(ah0.y), cvt_tf32(ah0.z), cvt_tf32(ah0.w)};
            uint32_t ual1[4] = {cvt_tf32(al1.x), cvt_tf32(al1.y), cvt_tf32(al1.z), cvt_tf32(al1.w)};
            uint32_t uah1[4] = {cvt_tf32(ah1.x), cvt_tf32(ah1.y), cvt_tf32(ah1.z), cvt_tf32(ah1.w)};

#pragma unroll
            for (int s = 0; s < 4; ++s) {
                uint32_t a[4] = {ual0[s], ual1[s], uah0[s], uah1[s]};
#pragma unroll
                for (int j = 0; j < 8; ++j) {
                    const float* fl = (const float*)&vbl[j];
                    const float* fh = (const float*)&vbh[j];
                    uint32_t b[2] = {__float_as_uint(fl[s]), __float_as_uint(fh[s])};
                    mma_tf32(acc[i][j], a, b);
                }
            }
        }
        __syncthreads();
    }

    // epilogue
#pragma unroll
    for (int i = 0; i < 4; ++i) {
        int row = m0 + wm * 64 + i * 16 + g;
#pragma unroll
        for (int j = 0; j < 8; ++j) {
            int col = n0 + wn * 64 + j * 8 + t * 2;
            *(float2*)(Y + (size_t)row * N + col) =
                make_float2(acc[i][j][0], acc[i][j][1]);
            *(float2*)(Y + (size_t)(row + 8) * N + col) =
                make_float2(acc[i][j][2], acc[i][j][3]);
        }
    }
}

// ---------------------------------------------------------------------------
// Kernel 3: in-place RMSNorm over rows of 1024 of d_out
// ---------------------------------------------------------------------------
__global__ __launch_bounds__(256) void rmsnorm_kernel(const float* __restrict__ nw,
                                                      float* __restrict__ out) {
    __shared__ float red[8];
    const int row = blockIdx.x;
    const int tt = threadIdx.x;
    float4* y4 = (float4*)(out + (size_t)row * N);
    float4 v = y4[tt];
    float ss = v.x * v.x + v.y * v.y + v.z * v.z + v.w * v.w;
#pragma unroll
    for (int o = 16; o; o >>= 1) ss += __shfl_xor_sync(0xFFFFFFFFu, ss, o);
    if ((tt & 31) == 0) red[tt >> 5] = ss;
    __syncthreads();
    float tot = red[0] + red[1] + red[2] + red[3] +
                red[4] + red[5] + red[6] + red[7];
    float sc = rsqrtf(tot * (1.0f / (float)N) + 1e-6f);
    float4 w = ((const float4*)nw)[tt];
    y4[tt] = make_float4(v.x * sc * w.x, v.y * sc * w.y,
                         v.z * sc * w.z, v.w * sc * w.w);
}

// ---------------------------------------------------------------------------
// Launch
// ---------------------------------------------------------------------------
extern "C" void kernel_launch(void* const* d_in, const int* in_sizes, int n_in,
                              void* d_out, int out_size) {
    (void)in_sizes; (void)n_in; (void)out_size;
    const float* x  = (const float*)d_in[0];
    const float* cw = (const float*)d_in[1];
    const float* nw = (const float*)d_in[2];
    float* out = (float*)d_out;

    (void)cudaGetLastError();   // clear any stale sticky error from setup

    cudaFuncSetAttribute(gemm_tf32_kernel,
                         cudaFuncAttributeMaxDynamicSharedMemorySize, SMEM_BYTES);

    reduce_w_kernel<<<(N * K / 4) / 256, 256>>>((const float4*)cw);
    gemm_tf32_kernel<<<dim3(N / BN, M / BM), 256, SMEM_BYTES>>>(x, out);
    rmsnorm_kernel<<<M, 256>>>(nw, out);
}

// round 13
// speedup vs baseline: 1.4776x; 1.4776x over previous
#include <cuda_runtime.h>
#include <cuda_fp16.h>
#include <cstdint>

// ---------------------------------------------------------------------------
// out = RMSNorm( x @ (mean_l conv_w[l])^T ) * norm_w
// R13 = R11 resubmit (R11/R12: broker acquisition timeouts, never ran):
// GEMM in fp16 mma.sync m16n8k16 (2x tensor rate vs tf32, same 10-bit
// mantissa; measured tf32 rel_err was 2.9e-4). x and W pre-converted to
// fp16 in DRAM-bound prep kernels.
// ---------------------------------------------------------------------------

static constexpr int M = 16384;
static constexpr int N = 1024;
static constexpr int K = 1024;
static constexpr int L = 20;

static constexpr int BM = 128;
static constexpr int BN = 256;
static constexpr int BK = 32;                          // fp16: row = 64 bytes
static constexpr int NKIT = K / BK;                    // 32

static constexpr int ROWB = 64;                        // bytes per smem row
static constexpr int A_BYTES = BM * ROWB;              // 8192
static constexpr int B_BYTES = BN * ROWB;              // 16384
static constexpr int STAGE_BYTES = A_BYTES + B_BYTES;  // 24576
static constexpr int NSTAGE = 4;
static constexpr int SMEM_BYTES = NSTAGE * STAGE_BYTES; // 98304

// Scratch (device globals: allocation-free rule)
__device__ __align__(16) __half g_Wh[N * K];           // 2 MB, fp16 W
__device__ __align__(16) __half g_Xh[M * K];           // 32 MB, fp16 x

// ---------------------------------------------------------------------------
// helpers
// ---------------------------------------------------------------------------
__device__ __forceinline__ uint32_t smem_u32(const void* p) {
    uint32_t a;
    asm("{ .reg .u64 t; cvta.to.shared.u64 t, %1; cvt.u32.u64 %0, t; }"
        : "=r"(a) : "l"(p));
    return a;
}

__device__ __forceinline__ void mma_f16(float* c, uint32_t a0, uint32_t a1,
                                        uint32_t a2, uint32_t a3,
                                        uint32_t b0, uint32_t b1) {
    asm volatile(
        "mma.sync.aligned.m16n8k16.row.col.f32.f16.f16.f32 "
        "{%0,%1,%2,%3}, {%4,%5,%6,%7}, {%8,%9}, {%0,%1,%2,%3};"
        : "+f"(c[0]), "+f"(c[1]), "+f"(c[2]), "+f"(c[3])
        : "r"(a0), "r"(a1), "r"(a2), "r"(a3), "r"(b0), "r"(b1));
}

__device__ __forceinline__ void cp_async16(uint32_t dst_smem, const void* src) {
    asm volatile("cp.async.cg.shared.global [%0], [%1], 16;"
                 :: "r"(dst_smem), "l"(src));
}
__device__ __forceinline__ void cp_commit() {
    asm volatile("cp.async.commit_group;" ::: "memory");
}
template <int NN>
__device__ __forceinline__ void cp_wait() {
    asm volatile("cp.async.wait_group %0;" :: "n"(NN) : "memory");
}

// ---------------------------------------------------------------------------
// Kernel 1: W fp16 = rn( (1/L) * sum_l conv_w[l] )
// ---------------------------------------------------------------------------
__global__ __launch_bounds__(256) void reduce_w_kernel(const float4* __restrict__ cw) {
    int idx = blockIdx.x * 256 + threadIdx.x;          // 0 .. 262143 (float4s)
    float4 acc = make_float4(0.f, 0.f, 0.f, 0.f);
#pragma unroll
    for (int l = 0; l < L; ++l) {
        float4 v = cw[(size_t)l * (N * K / 4) + idx];
        acc.x += v.x; acc.y += v.y; acc.z += v.z; acc.w += v.w;
    }
    const float s = 1.0f / (float)L;
    __half2 h0 = __floats2half2_rn(acc.x * s, acc.y * s);
    __half2 h1 = __floats2half2_rn(acc.z * s, acc.w * s);
    ((__half2*)g_Wh)[idx * 2]     = h0;
    ((__half2*)g_Wh)[idx * 2 + 1] = h1;
}

// ---------------------------------------------------------------------------
// Kernel 1b: x fp32 -> fp16
// ---------------------------------------------------------------------------
__global__ __launch_bounds__(256) void convert_x_kernel(const float4* __restrict__ x) {
    int idx = blockIdx.x * 256 + threadIdx.x;          // 0 .. M*K/4-1
    float4 v = x[idx];
    __half2 h0 = __floats2half2_rn(v.x, v.y);
    __half2 h1 = __floats2half2_rn(v.z, v.w);
    ((__half2*)g_Xh)[idx * 2]     = h0;
    ((__half2*)g_Xh)[idx * 2 + 1] = h1;
}

// ---------------------------------------------------------------------------
// Kernel 2: fp16 mma.sync GEMM  y = x @ W^T  -> d_out (f32)
//   CTA 128x256x32, 8 warps at 64x64, 4-stage cp.async.
//   smem row = 32 fp16 = 4 x 16B chunks; chunk s stored at s ^ (row&3).
//   K-permutation: thread t's local k-positions {2t,2t+1,2t+8,2t+9} of the
//   two k16 slices map to global columns {8t..8t+7} -> one LDS.128 per row
//   covers both slices. A and B share the permutation, so the contraction
//   stays aligned.
// ---------------------------------------------------------------------------
__global__ __launch_bounds__(256, 1) void gemm_f16_kernel(float* __restrict__ Y) {
    extern __shared__ __align__(16) char smem[];
    const int tid = threadIdx.x;
    const int wid = tid >> 5;
    const int lid = tid & 31;
    const int g = lid >> 2;      // 0..7
    const int t = lid & 3;       // 0..3
    const int wm = wid >> 2;     // 0..1
    const int wn = wid & 3;      // 0..3

    const int n0 = blockIdx.x * BN;
    const int m0 = blockIdx.y * BM;

    const uint32_t sbase = smem_u32(smem);

    float acc[4][8][4];
#pragma unroll
    for (int i = 0; i < 4; ++i)
#pragma unroll
        for (int j = 0; j < 8; ++j)
#pragma unroll
            for (int q = 0; q < 4; ++q) acc[i][j][q] = 0.f;

    const __half* Abase = g_Xh + (size_t)m0 * K;
    const __half* Bbase = g_Wh + (size_t)n0 * K;

    auto load_tiles = [&](int kt, int stage) {
        const uint32_t sA = sbase + stage * STAGE_BYTES;
        const uint32_t sB = sA + A_BYTES;
        const __half* Ak = Abase + kt * BK;
        const __half* Bk = Bbase + kt * BK;
#pragma unroll
        for (int q = 0; q < 2; ++q) {                  // A: 512 chunks
            int id = tid + q * 256;
            int row = id >> 2, s = id & 3;
            int phys = s ^ (row & 3);
            cp_async16(sA + (uint32_t)(row * ROWB + phys * 16),
                       Ak + (size_t)row * K + s * 8);
        }
#pragma unroll
        for (int q = 0; q < 4; ++q) {                  // B: 1024 chunks
            int id = tid + q * 256;
            int row = id >> 2, s = id & 3;
            int phys = s ^ (row & 3);
            cp_async16(sB + (uint32_t)(row * ROWB + phys * 16),
                       Bk + (size_t)row * K + s * 8);
        }
        cp_commit();
    };

    load_tiles(0, 0);
    load_tiles(1, 1);
    load_tiles(2, 2);

    const int cc = t ^ (g & 3);         // physical chunk for this thread's 16B

#pragma unroll 1
    for (int kt = 0; kt < NKIT; ++kt) {
        if (kt + 3 < NKIT) load_tiles(kt + 3, (kt + 3) & 3);

        if (kt < NKIT - 3)       cp_wait<3>();
        else if (kt == NKIT - 3) cp_wait<2>();
        else if (kt == NKIT - 2) cp_wait<1>();
        else                     cp_wait<0>();
        __syncthreads();

        const char* As = smem + (kt & 3) * STAGE_BYTES;
        const char* Bs = As + A_BYTES;

        // A fragments resident: 4 m-blocks x rows {r, r+8}, 16B each
        uint4 qa[4], pa[4];
#pragma unroll
        for (int i = 0; i < 4; ++i) {
            int r = wm * 64 + i * 16 + g;              // r & 3 == g & 3
            qa[i] = *(const uint4*)(As + r * ROWB + cc * 16);
            pa[i] = *(const uint4*)(As + (r + 8) * ROWB + cc * 16);
        }

#pragma unroll
        for (int j = 0; j < 8; ++j) {
            int n = wn * 64 + j * 8 + g;               // n & 3 == g & 3
            uint4 vb = *(const uint4*)(Bs + n * ROWB + cc * 16);
#pragma unroll
            for (int i = 0; i < 4; ++i) {
                // slice 0: global cols {8t..8t+3}
                mma_f16(acc[i][j], qa[i].x, pa[i].x, qa[i].y, pa[i].y,
                        vb.x, vb.y);
                // slice 1: global cols {8t+4..8t+7}
                mma_f16(acc[i][j], qa[i].z, pa[i].z, qa[i].w, pa[i].w,
                        vb.z, vb.w);
            }
        }
        __syncthreads();
    }

    // epilogue: f32 result to Y (d_out)
#pragma unroll
    for (int i = 0; i < 4; ++i) {
        int row = m0 + wm * 64 + i * 16 + g;
#pragma unroll
        for (int j = 0; j < 8; ++j) {
            int col = n0 + wn * 64 + j * 8 + t * 2;
            *(float2*)(Y + (size_t)row * N + col) =
                make_float2(acc[i][j][0], acc[i][j][1]);
            *(float2*)(Y + (size_t)(row + 8) * N + col) =
                make_float2(acc[i][j][2], acc[i][j][3]);
        }
    }
}

// ---------------------------------------------------------------------------
// Kernel 3: in-place RMSNorm over rows of 1024 of d_out
// ---------------------------------------------------------------------------
__global__ __launch_bounds__(256) void rmsnorm_kernel(const float* __restrict__ nw,
                                                      float* __restrict__ out) {
    __shared__ float red[8];
    const int row = blockIdx.x;
    const int tt = threadIdx.x;
    float4* y4 = (float4*)(out + (size_t)row * N);
    float4 v = y4[tt];
    float ss = v.x * v.x + v.y * v.y + v.z * v.z + v.w * v.w;
#pragma unroll
    for (int o = 16; o; o >>= 1) ss += __shfl_xor_sync(0xFFFFFFFFu, ss, o);
    if ((tt & 31) == 0) red[tt >> 5] = ss;
    __syncthreads();
    float tot = red[0] + red[1] + red[2] + red[3] +
                red[4] + red[5] + red[6] + red[7];
    float sc = rsqrtf(tot * (1.0f / (float)N) + 1e-6f);
    float4 w = ((const float4*)nw)[tt];
    y4[tt] = make_float4(v.x * sc * w.x, v.y * sc * w.y,
                         v.z * sc * w.z, v.w * sc * w.w);
}

// ---------------------------------------------------------------------------
// Launch
// ---------------------------------------------------------------------------
extern "C" void kernel_launch(void* const* d_in, const int* in_sizes, int n_in,
                              void* d_out, int out_size) {
    (void)in_sizes; (void)n_in; (void)out_size;
    const float* x  = (const float*)d_in[0];
    const float* cw = (const float*)d_in[1];
    const float* nw = (const float*)d_in[2];
    float* out = (float*)d_out;

    (void)cudaGetLastError();

    cudaFuncSetAttribute(gemm_f16_kernel,
                         cudaFuncAttributeMaxDynamicSharedMemorySize, SMEM_BYTES);

    reduce_w_kernel<<<(N * K / 4) / 256, 256>>>((const float4*)cw);
    convert_x_kernel<<<(M * K / 4) / 256, 256>>>((const float4*)x);
    gemm_f16_kernel<<<dim3(N / BN, M / BM), 256, SMEM_BYTES>>>(out);
    rmsnorm_kernel<<<M, 256>>>(nw, out);
}

// round 16
// speedup vs baseline: 1.6515x; 1.1177x over previous
#include <cuda_runtime.h>
#include <cuda_fp16.h>
#include <cstdint>

// ---------------------------------------------------------------------------
// out = RMSNorm( x @ (mean_l conv_w[l])^T ) * norm_w
// R16 = R14 resubmit (R14/R15: broker acquisition timeouts, never ran):
// fp16 GEMM retiled 128x128, occ=2 (fix wave quantization: 512 CTAs @ occ1
// = 3.46 waves -> rounds to 4; now 1024 CTAs @ occ2, tail hidden by
// co-resident CTA). rmsnorm -> warp-per-row (no block barrier).
// ---------------------------------------------------------------------------

static constexpr int M = 16384;
static constexpr int N = 1024;
static constexpr int K = 1024;
static constexpr int L = 20;

static constexpr int BM = 128;
static constexpr int BN = 128;
static constexpr int BK = 32;                          // fp16: row = 64 bytes
static constexpr int NKIT = K / BK;                    // 32

static constexpr int ROWB = 64;                        // bytes per smem row
static constexpr int A_BYTES = BM * ROWB;              // 8192
static constexpr int B_BYTES = BN * ROWB;              // 8192
static constexpr int STAGE_BYTES = A_BYTES + B_BYTES;  // 16384
static constexpr int NSTAGE = 4;
static constexpr int SMEM_BYTES = NSTAGE * STAGE_BYTES; // 65536 -> occ 2

// Scratch (device globals: allocation-free rule)
__device__ __align__(16) __half g_Wh[N * K];           // 2 MB, fp16 W
__device__ __align__(16) __half g_Xh[M * K];           // 32 MB, fp16 x

// ---------------------------------------------------------------------------
// helpers
// ---------------------------------------------------------------------------
__device__ __forceinline__ uint32_t smem_u32(const void* p) {
    uint32_t a;
    asm("{ .reg .u64 t; cvta.to.shared.u64 t, %1; cvt.u32.u64 %0, t; }"
        : "=r"(a) : "l"(p));
    return a;
}

__device__ __forceinline__ void mma_f16(float* c, uint32_t a0, uint32_t a1,
                                        uint32_t a2, uint32_t a3,
                                        uint32_t b0, uint32_t b1) {
    asm volatile(
        "mma.sync.aligned.m16n8k16.row.col.f32.f16.f16.f32 "
        "{%0,%1,%2,%3}, {%4,%5,%6,%7}, {%8,%9}, {%0,%1,%2,%3};"
        : "+f"(c[0]), "+f"(c[1]), "+f"(c[2]), "+f"(c[3])
        : "r"(a0), "r"(a1), "r"(a2), "r"(a3), "r"(b0), "r"(b1));
}

__device__ __forceinline__ void cp_async16(uint32_t dst_smem, const void* src) {
    asm volatile("cp.async.cg.shared.global [%0], [%1], 16;"
                 :: "r"(dst_smem), "l"(src));
}
__device__ __forceinline__ void cp_commit() {
    asm volatile("cp.async.commit_group;" ::: "memory");
}
template <int NN>
__device__ __forceinline__ void cp_wait() {
    asm volatile("cp.async.wait_group %0;" :: "n"(NN) : "memory");
}

// ---------------------------------------------------------------------------
// Kernel 1: W fp16 = rn( (1/L) * sum_l conv_w[l] )
// ---------------------------------------------------------------------------
__global__ __launch_bounds__(256) void reduce_w_kernel(const float4* __restrict__ cw) {
    int idx = blockIdx.x * 256 + threadIdx.x;          // float4 index
    float4 acc = make_float4(0.f, 0.f, 0.f, 0.f);
#pragma unroll
    for (int l = 0; l < L; ++l) {
        float4 v = cw[(size_t)l * (N * K / 4) + idx];
        acc.x += v.x; acc.y += v.y; acc.z += v.z; acc.w += v.w;
    }
    const float s = 1.0f / (float)L;
    __half2 h0 = __floats2half2_rn(acc.x * s, acc.y * s);
    __half2 h1 = __floats2half2_rn(acc.z * s, acc.w * s);
    ((__half2*)g_Wh)[idx * 2]     = h0;
    ((__half2*)g_Wh)[idx * 2 + 1] = h1;
}

// ---------------------------------------------------------------------------
// Kernel 1b: x fp32 -> fp16
// ---------------------------------------------------------------------------
__global__ __launch_bounds__(256) void convert_x_kernel(const float4* __restrict__ x) {
    int idx = blockIdx.x * 256 + threadIdx.x;
    float4 v = x[idx];
    __half2 h0 = __floats2half2_rn(v.x, v.y);
    __half2 h1 = __floats2half2_rn(v.z, v.w);
    ((__half2*)g_Xh)[idx * 2]     = h0;
    ((__half2*)g_Xh)[idx * 2 + 1] = h1;
}

// ---------------------------------------------------------------------------
// Kernel 2: fp16 mma.sync GEMM  y = x @ W^T  -> d_out (f32)
//   CTA 128x128x32, 8 warps as 2x4 at 64x32, 4-stage cp.async, occ=2.
//   smem row = 32 fp16 = 4 x 16B chunks; chunk s stored at s ^ (row&3).
//   K-permutation (A and B identically): thread t's two k16 slices cover
//   global columns {8t..8t+7} -> one LDS.128 per row covers both slices.
// ---------------------------------------------------------------------------
__global__ __launch_bounds__(256, 2) void gemm_f16_kernel(float* __restrict__ Y) {
    extern __shared__ __align__(16) char smem[];
    const int tid = threadIdx.x;
    const int wid = tid >> 5;
    const int lid = tid & 31;
    const int g = lid >> 2;      // 0..7
    const int t = lid & 3;       // 0..3
    const int wm = wid >> 2;     // 0..1 -> 64-row halves
    const int wn = wid & 3;      // 0..3 -> 32-col quarters

    const int n0 = blockIdx.x * BN;
    const int m0 = blockIdx.y * BM;

    const uint32_t sbase = smem_u32(smem);

    float acc[4][4][4];
#pragma unroll
    for (int i = 0; i < 4; ++i)
#pragma unroll
        for (int j = 0; j < 4; ++j)
#pragma unroll
            for (int q = 0; q < 4; ++q) acc[i][j][q] = 0.f;

    const __half* Abase = g_Xh + (size_t)m0 * K;
    const __half* Bbase = g_Wh + (size_t)n0 * K;

    auto load_tiles = [&](int kt, int stage) {
        const uint32_t sA = sbase + stage * STAGE_BYTES;
        const uint32_t sB = sA + A_BYTES;
        const __half* Ak = Abase + kt * BK;
        const __half* Bk = Bbase + kt * BK;
#pragma unroll
        for (int q = 0; q < 2; ++q) {                  // A: 512 chunks
            int id = tid + q * 256;
            int row = id >> 2, s = id & 3;
            int phys = s ^ (row & 3);
            cp_async16(sA + (uint32_t)(row * ROWB + phys * 16),
                       Ak + (size_t)row * K + s * 8);
        }
#pragma unroll
        for (int q = 0; q < 2; ++q) {                  // B: 512 chunks
            int id = tid + q * 256;
            int row = id >> 2, s = id & 3;
            int phys = s ^ (row & 3);
            cp_async16(sB + (uint32_t)(row * ROWB + phys * 16),
                       Bk + (size_t)row * K + s * 8);
        }
        cp_commit();
    };

    load_tiles(0, 0);
    load_tiles(1, 1);
    load_tiles(2, 2);

    const int cc = t ^ (g & 3);         // physical chunk for this thread's 16B

#pragma unroll 1
    for (int kt = 0; kt < NKIT; ++kt) {
        if (kt + 3 < NKIT) load_tiles(kt + 3, (kt + 3) & 3);

        if (kt < NKIT - 3)       cp_wait<3>();
        else if (kt == NKIT - 3) cp_wait<2>();
        else if (kt == NKIT - 2) cp_wait<1>();
        else                     cp_wait<0>();
        __syncthreads();

        const char* As = smem + (kt & 3) * STAGE_BYTES;
        const char* Bs = As + A_BYTES;

        // A fragments: 4 m-blocks x rows {r, r+8}
        uint4 qa[4], pa[4];
#pragma unroll
        for (int i = 0; i < 4; ++i) {
            int r = wm * 64 + i * 16 + g;              // r & 3 == g & 3
            qa[i] = *(const uint4*)(As + r * ROWB + cc * 16);
            pa[i] = *(const uint4*)(As + (r + 8) * ROWB + cc * 16);
        }

#pragma unroll
        for (int j = 0; j < 4; ++j) {
            int n = wn * 32 + j * 8 + g;               // n & 3 == g & 3
            uint4 vb = *(const uint4*)(Bs + n * ROWB + cc * 16);
#pragma unroll
            for (int i = 0; i < 4; ++i) {
                mma_f16(acc[i][j], qa[i].x, pa[i].x, qa[i].y, pa[i].y,
                        vb.x, vb.y);
                mma_f16(acc[i][j], qa[i].z, pa[i].z, qa[i].w, pa[i].w,
                        vb.z, vb.w);
            }
        }
        __syncthreads();
    }

    // epilogue: f32 result to Y (d_out)
#pragma unroll
    for (int i = 0; i < 4; ++i) {
        int row = m0 + wm * 64 + i * 16 + g;
#pragma unroll
        for (int j = 0; j < 4; ++j) {
            int col = n0 + wn * 32 + j * 8 + t * 2;
            *(float2*)(Y + (size_t)row * N + col) =
                make_float2(acc[i][j][0], acc[i][j][1]);
            *(float2*)(Y + (size_t)(row + 8) * N + col) =
                make_float2(acc[i][j][2], acc[i][j][3]);
        }
    }
}

// ---------------------------------------------------------------------------
// Kernel 3: in-place RMSNorm, one WARP per row (no block barrier).
//   lane reads 8 float4 strided by 32 -> coalesced; shuffle-only reduction.
// ---------------------------------------------------------------------------
__global__ __launch_bounds__(256) void rmsnorm_kernel(const float* __restrict__ nw,
                                                      float* __restrict__ out) {
    const int w = threadIdx.x >> 5;                    // warp in block: 0..7
    const int lane = threadIdx.x & 31;
    const int row = blockIdx.x * 8 + w;
    float4* y4 = (float4*)(out + (size_t)row * N);
    const float4* nw4 = (const float4*)nw;

    float4 v[8];
    float ss = 0.f;
#pragma unroll
    for (int q = 0; q < 8; ++q) {
        v[q] = y4[lane + q * 32];
        ss += v[q].x * v[q].x + v[q].y * v[q].y +
              v[q].z * v[q].z + v[q].w * v[q].w;
    }
#pragma unroll
    for (int o = 16; o; o >>= 1) ss += __shfl_xor_sync(0xFFFFFFFFu, ss, o);
    float sc = rsqrtf(ss * (1.0f / (float)N) + 1e-6f);
#pragma unroll
    for (int q = 0; q < 8; ++q) {
        float4 wv = nw4[lane + q * 32];
        y4[lane + q * 32] = make_float4(v[q].x * sc * wv.x, v[q].y * sc * wv.y,
                                        v[q].z * sc * wv.z, v[q].w * sc * wv.w);
    }
}

// ---------------------------------------------------------------------------
// Launch
// ---------------------------------------------------------------------------
extern "C" void kernel_launch(void* const* d_in, const int* in_sizes, int n_in,
                              void* d_out, int out_size) {
    (void)in_sizes; (void)n_in; (void)out_size;
    const float* x  = (const float*)d_in[0];
    const float* cw = (const float*)d_in[1];
    const float* nw = (const float*)d_in[2];
    float* out = (float*)d_out;

    (void)cudaGetLastError();

    cudaFuncSetAttribute(gemm_f16_kernel,
                         cudaFuncAttributeMaxDynamicSharedMemorySize, SMEM_BYTES);

    reduce_w_kernel<<<(N * K / 4) / 256, 256>>>((const float4*)cw);
    convert_x_kernel<<<(M * K / 4) / 256, 256>>>((const float4*)x);
    gemm_f16_kernel<<<dim3(N / BN, M / BM), 256, SMEM_BYTES>>>(out);
    rmsnorm_kernel<<<M / 8, 256>>>(nw, out);
}